// round 16
// baseline (speedup 1.0000x reference)
#include <cuda_runtime.h>
#include <cuda_fp16.h>
#include <math.h>
#include <stdint.h>

// ---------------- constants ----------------
#define Bb 4
#define Ss 1024
#define Tt 4096
#define Dd 1024
#define Hh 16
#define HDd 64
#define Ee 8
#define Ff 4096
#define CAP 4096
#define EPSf 1e-6f

#define RS  72             // A-tile smem row stride (halves), k64
#define RSB 136            // B-tile ([K][N]) smem row stride (halves)

// k64 stage layouts (halves)
#define OFB  9216          // dense/down: A[128][72] then B[64][136]
#define STEd 17920
#define OFG  9216          // gu: A[128][72], G[64][136], U[64][136]
#define OFU  17920
#define STEg 26624

#define SMEMd (2 * STEd * 2)    // 71680 B (2-stage, 2 CTA/SM)
#define SMEMg3 (3 * STEg * 2)   // 159744 B (3-stage, 1 CTA/SM)

// fmha smem (halves): Q[128][72], K0,V0,K1,V1 each [128][72]
#define FK0 9216
#define FV0 18432
#define FKV 18432
#define SMEMf (46080 * 2)

// ---------------- scratch ----------------
__device__ __align__(256) float g_hidden[(size_t)Tt * Dd];
__device__ __align__(256) __half g_moeout16[(size_t)Ee * CAP * Dd];
__device__ float g_topw[Tt * 2];
__device__ int   g_slotid[Tt * 2];
__device__ int   g_cnt[Ee];
__device__ int   g_assign[Ee * CAP];

__device__ __align__(256) __half g_x16[(size_t)Tt * Dd];
__device__ __align__(256) __half g_q16[(size_t)Tt * Dd];
__device__ __align__(256) __half g_k16[(size_t)Tt * Dd];
__device__ __align__(256) __half g_v16[(size_t)Tt * Dd];
__device__ __align__(256) __half g_o16[(size_t)Tt * Dd];
__device__ __align__(256) __half g_xt16[(size_t)Tt * Dd];
__device__ __align__(256) __half g_h16[(size_t)Ee * CAP * Ff];

// fp16 weights, ORIGINAL layout [K][N]
__device__ __align__(256) __half g_Wg16[(size_t)Ee * Dd * Ff];
__device__ __align__(256) __half g_Wu16[(size_t)Ee * Dd * Ff];
__device__ __align__(256) __half g_Wd16[(size_t)Ee * Ff * Dd];
__device__ __align__(256) __half g_Wq16[(size_t)Dd * Dd];
__device__ __align__(256) __half g_Wk16[(size_t)Dd * Dd];
__device__ __align__(256) __half g_Wv16[(size_t)Dd * Dd];
__device__ __align__(256) __half g_Wo16[(size_t)Dd * Dd];

// ---------------- helpers ----------------
__device__ __forceinline__ float warp_red_sum(float v) {
#pragma unroll
    for (int o = 16; o; o >>= 1) v += __shfl_xor_sync(0xffffffffu, v, o);
    return v;
}
__device__ __forceinline__ uint32_t smem_u32(const void* p) {
    uint32_t a;
    asm("{ .reg .u64 t; cvta.to.shared.u64 t, %1; cvt.u32.u64 %0, t; }" : "=r"(a) : "l"(p));
    return a;
}
#define CP16(sm, gp) \
    asm volatile("cp.async.ca.shared.global [%0], [%1], 16;" :: "r"(sm), "l"(gp))
#define CPCOMMIT() asm volatile("cp.async.commit_group;")
#define CPWAIT1() asm volatile("cp.async.wait_group 1;")
#define CPWAIT2() asm volatile("cp.async.wait_group 2;")

__device__ __forceinline__ void ldm4(uint32_t* r, uint32_t addr) {
    asm volatile("ldmatrix.sync.aligned.m8n8.x4.shared.b16 {%0,%1,%2,%3}, [%4];"
                 : "=r"(r[0]), "=r"(r[1]), "=r"(r[2]), "=r"(r[3]) : "r"(addr));
}
__device__ __forceinline__ void ldm4t(uint32_t* r, uint32_t addr) {
    asm volatile("ldmatrix.sync.aligned.m8n8.x4.trans.shared.b16 {%0,%1,%2,%3}, [%4];"
                 : "=r"(r[0]), "=r"(r[1]), "=r"(r[2]), "=r"(r[3]) : "r"(addr));
}
__device__ __forceinline__ void mma_f16(float* c, const uint32_t* a, const uint32_t* b) {
    asm volatile(
        "mma.sync.aligned.m16n8k16.row.col.f32.f16.f16.f32 "
        "{%0,%1,%2,%3},{%4,%5,%6,%7},{%8,%9},{%0,%1,%2,%3};"
        : "+f"(c[0]), "+f"(c[1]), "+f"(c[2]), "+f"(c[3])
        : "r"(a[0]), "r"(a[1]), "r"(a[2]), "r"(a[3]), "r"(b[0]), "r"(b[1]));
}
__device__ __forceinline__ uint32_t pack_h2(float a, float b) {
    __half2 h; h.x = __float2half_rn(a); h.y = __float2half_rn(b);
    return *(uint32_t*)&h;
}
// fast exp on FMA pipe (rel err ~4e-5)
__device__ __forceinline__ float fexp(float x) {
    x = fminf(fmaxf(x, -60.f), 60.f);
    float z = x * 1.442695041f;
    float j = z + 12582912.f;
    int i = __float_as_int(j) - 0x4b400000;
    float f = z - (j - 12582912.f);
    float p = fmaf(f, 0.009618129f, 0.055504110f);
    p = fmaf(f, p, 0.240226507f);
    p = fmaf(f, p, 0.693147181f);
    p = fmaf(f, p, 1.0f);
    return __int_as_float(__float_as_int(p) + (i << 23));
}
__device__ __forceinline__ float frcp(float d) {
    float r = __uint_as_float(0x7ef311c3u - __float_as_uint(d));
    r = r * (2.0f - d * r);
    r = r * (2.0f - d * r);
    r = r * (2.0f - d * r);
    return r;
}

// ---------------- streaming weight convert fp32 -> fp16 (8 elems/thread) ----------------
__global__ void wconv_k(const float* __restrict__ in, __half* __restrict__ o) {
    const size_t i = ((size_t)blockIdx.x * 256 + threadIdx.x) * 8;
    float4 a = *(const float4*)(in + i);
    float4 b = *(const float4*)(in + i + 4);
    uint4 p;
    p.x = pack_h2(a.x, a.y);
    p.y = pack_h2(a.z, a.w);
    p.z = pack_h2(b.x, b.y);
    p.w = pack_h2(b.z, b.w);
    *(uint4*)(o + i) = p;
}

// batched small converts: z selects (Wq,Wk,Wv,Wo)
__global__ void wconv4_k(const float* __restrict__ wq, const float* __restrict__ wk,
                         const float* __restrict__ wv, const float* __restrict__ wo) {
    const float* in;
    __half* o;
    switch (blockIdx.z) {
        case 0: in = wq; o = g_Wq16; break;
        case 1: in = wk; o = g_Wk16; break;
        case 2: in = wv; o = g_Wv16; break;
        default: in = wo; o = g_Wo16; break;
    }
    const size_t i = ((size_t)blockIdx.x * 256 + threadIdx.x) * 8;
    float4 a = *(const float4*)(in + i);
    float4 b = *(const float4*)(in + i + 4);
    uint4 p;
    p.x = pack_h2(a.x, a.y);
    p.y = pack_h2(a.z, a.w);
    p.z = pack_h2(b.x, b.y);
    p.w = pack_h2(b.z, b.w);
    *(uint4*)(o + i) = p;
}

// ---------------- RMSNorm -> fp16 ----------------
__global__ void rmsnorm_h(const float* __restrict__ in, const float* __restrict__ w,
                          __half* __restrict__ o16) {
    const int t = blockIdx.x;
    const float* x = in + (size_t)t * Dd;
    float ss = 0.f;
    float v4[4];
#pragma unroll
    for (int j = 0; j < 4; j++) {
        float v = x[threadIdx.x + j * 256];
        v4[j] = v;
        ss = fmaf(v, v, ss);
    }
    __shared__ float red[8];
    __shared__ float sres;
    float ws = warp_red_sum(ss);
    if ((threadIdx.x & 31) == 0) red[threadIdx.x >> 5] = ws;
    __syncthreads();
    if (threadIdx.x == 0) {
        float s = 0.f;
        for (int i = 0; i < 8; i++) s += red[i];
        sres = rsqrtf(s * (1.f / Dd) + EPSf);
    }
    __syncthreads();
    const float r = sres;
#pragma unroll
    for (int j = 0; j < 4; j++) {
        int i = threadIdx.x + j * 256;
        o16[(size_t)t * Dd + i] = __float2half_rn(v4[j] * r * w[i]);
    }
}

// ---------------- fused RMSNorm + router + slot assignment (block = token) ----------------
__global__ void rmsnorm_router_k(const float* __restrict__ in, const float* __restrict__ w,
                                 const float* __restrict__ Gw, __half* __restrict__ o16,
                                 float* __restrict__ logits_out, int write_logits) {
    const int t = blockIdx.x;
    const int tid = threadIdx.x;
    const float* x = in + (size_t)t * Dd;
    float ss = 0.f;
    float v4[4];
#pragma unroll
    for (int j = 0; j < 4; j++) {
        float v = x[tid + j * 256];
        v4[j] = v;
        ss = fmaf(v, v, ss);
    }
    __shared__ float red[8];
    __shared__ float red8[8][8];
    __shared__ float lgs[8];
    __shared__ float sres;
    float ws = warp_red_sum(ss);
    if ((tid & 31) == 0) red[tid >> 5] = ws;
    __syncthreads();
    if (tid == 0) {
        float s = 0.f;
        for (int i = 0; i < 8; i++) s += red[i];
        sres = rsqrtf(s * (1.f / Dd) + EPSf);
    }
    __syncthreads();
    const float r = sres;
    float s[8];
#pragma unroll
    for (int e = 0; e < 8; e++) s[e] = 0.f;
#pragma unroll
    for (int j = 0; j < 4; j++) {
        int i = tid + j * 256;
        float v = v4[j] * r * w[i];
        o16[(size_t)t * Dd + i] = __float2half_rn(v);
        float4 g0 = *(const float4*)(Gw + (size_t)i * 8);
        float4 g1 = *(const float4*)(Gw + (size_t)i * 8 + 4);
        s[0] = fmaf(v, g0.x, s[0]); s[1] = fmaf(v, g0.y, s[1]);
        s[2] = fmaf(v, g0.z, s[2]); s[3] = fmaf(v, g0.w, s[3]);
        s[4] = fmaf(v, g1.x, s[4]); s[5] = fmaf(v, g1.y, s[5]);
        s[6] = fmaf(v, g1.z, s[6]); s[7] = fmaf(v, g1.w, s[7]);
    }
#pragma unroll
    for (int e = 0; e < 8; e++) s[e] = warp_red_sum(s[e]);
    if ((tid & 31) == 0) {
#pragma unroll
        for (int e = 0; e < 8; e++) red8[tid >> 5][e] = s[e];
    }
    __syncthreads();
    if (tid == 0) {
        float lg[8];
#pragma unroll
        for (int e = 0; e < 8; e++) {
            float a = 0.f;
            for (int wdx = 0; wdx < 8; wdx++) a += red8[wdx][e];
            lg[e] = a;
            lgs[e] = a;
        }
        float mx = lg[0];
#pragma unroll
        for (int e = 1; e < 8; e++) mx = fmaxf(mx, lg[e]);
        float p[8];
        float sum = 0.f;
#pragma unroll
        for (int e = 0; e < 8; e++) { p[e] = __expf(lg[e] - mx); sum += p[e]; }
        int i0 = 0;
#pragma unroll
        for (int e = 1; e < 8; e++) if (p[e] > p[i0]) i0 = e;
        int i1 = (i0 == 0) ? 1 : 0;
#pragma unroll
        for (int e = 0; e < 8; e++) if (e != i0 && p[e] > p[i1]) i1 = e;
        float v0 = p[i0] / sum, v1 = p[i1] / sum;
        float inv = 1.f / (v0 + v1);
        g_topw[t * 2 + 0] = v0 * inv;
        g_topw[t * 2 + 1] = v1 * inv;
        int pos0 = atomicAdd(&g_cnt[i0], 1);
        g_assign[i0 * CAP + pos0] = t;
        g_slotid[t * 2 + 0] = i0 * CAP + pos0;
        int pos1 = atomicAdd(&g_cnt[i1], 1);
        g_assign[i1 * CAP + pos1] = t;
        g_slotid[t * 2 + 1] = i1 * CAP + pos1;
    }
    __syncthreads();
    if (write_logits && tid < 8) logits_out[(size_t)t * 8 + tid] = lgs[tid];
}

// ---------------- shared dense-GEMM core (k64, 2-stage) ----------------
__device__ __forceinline__ void dense_core(
    const __half* __restrict__ A, const __half* __restrict__ B,
    float* __restrict__ Cf, __half* __restrict__ C16,
    const float* __restrict__ resid, const float* __restrict__ gamma,
    const float* __restrict__ nw, float nsc,
    int K, int N, int m0, int n0, char* smp) {
    const uint32_t sb = smem_u32(smp);
    const int tid = threadIdx.x, lane = tid & 31, wid = tid >> 5;
    const int wm = wid & 3, wn = wid >> 2;

    float acc[2][8][4];
#pragma unroll
    for (int a = 0; a < 2; a++)
#pragma unroll
        for (int b = 0; b < 8; b++)
#pragma unroll
            for (int c = 0; c < 4; c++) acc[a][b][c] = 0.f;

    const int ra = tid >> 3, ca = (tid & 7) << 3;
    const int rb = tid >> 4, cb = (tid & 15) << 3;
    {
        uint32_t base = sb;
#pragma unroll
        for (int i = 0; i < 4; i++)
            CP16(base + (uint32_t)((ra + i * 32) * RS + ca) * 2,
                 A + (size_t)(m0 + ra + i * 32) * K + ca);
#pragma unroll
        for (int i = 0; i < 4; i++)
            CP16(base + (uint32_t)(OFB + (rb + i * 16) * RSB + cb) * 2,
                 B + (size_t)(rb + i * 16) * N + n0 + cb);
        CPCOMMIT();
    }
    const int nb = K >> 6;
    for (int it = 0; it < nb; it++) {
        if (it + 1 < nb) {
            uint32_t base = sb + (uint32_t)((it + 1) & 1) * STEd * 2;
            int k0 = (it + 1) << 6;
#pragma unroll
            for (int i = 0; i < 4; i++)
                CP16(base + (uint32_t)((ra + i * 32) * RS + ca) * 2,
                     A + (size_t)(m0 + ra + i * 32) * K + k0 + ca);
#pragma unroll
            for (int i = 0; i < 4; i++)
                CP16(base + (uint32_t)(OFB + (rb + i * 16) * RSB + cb) * 2,
                     B + (size_t)(k0 + rb + i * 16) * N + n0 + cb);
        }
        CPCOMMIT();
        CPWAIT1();
        __syncthreads();
        uint32_t base = sb + (uint32_t)(it & 1) * STEd * 2;
#pragma unroll
        for (int ks = 0; ks < 4; ks++) {
            uint32_t a[2][4];
#pragma unroll
            for (int mt = 0; mt < 2; mt++)
                ldm4(a[mt], base + (uint32_t)((wm * 32 + mt * 16 + (lane & 15)) * RS +
                                              ks * 16 + (lane >> 4) * 8) * 2);
            uint32_t bq[4][4];
#pragma unroll
            for (int bt = 0; bt < 4; bt++)
                ldm4t(bq[bt], base + (uint32_t)(OFB +
                                                (ks * 16 + (lane & 7) + ((lane >> 3) & 1) * 8) * RSB +
                                                wn * 64 + bt * 16 + (lane >> 4) * 8) * 2);
#pragma unroll
            for (int mt = 0; mt < 2; mt++)
#pragma unroll
                for (int nt = 0; nt < 8; nt++)
                    mma_f16(acc[mt][nt], a[mt], &bq[nt >> 1][(nt & 1) * 2]);
        }
        __syncthreads();
    }
    const int lr = lane >> 2, lc2 = (lane & 3) * 2;
    if (C16 && nw) {
#pragma unroll
        for (int mt = 0; mt < 2; mt++)
#pragma unroll
            for (int half = 0; half < 2; half++) {
                float ss = 0.f;
#pragma unroll
                for (int nt = 0; nt < 8; nt++) {
                    float a0 = acc[mt][nt][half * 2], a1 = acc[mt][nt][half * 2 + 1];
                    ss = fmaf(a0, a0, fmaf(a1, a1, ss));
                }
                ss += __shfl_xor_sync(0xffffffffu, ss, 1);
                ss += __shfl_xor_sync(0xffffffffu, ss, 2);
                float r = rsqrtf(ss * (1.f / HDd) + EPSf) * nsc;
                int row = m0 + wm * 32 + mt * 16 + lr + half * 8;
#pragma unroll
                for (int nt = 0; nt < 8; nt++) {
                    int wcol = nt * 8 + lc2;
                    int col = n0 + wn * 64 + wcol;
                    *(uint32_t*)(C16 + (size_t)row * N + col) =
                        pack_h2(acc[mt][nt][half * 2] * r * nw[wcol],
                                acc[mt][nt][half * 2 + 1] * r * nw[wcol + 1]);
                }
            }
    } else {
#pragma unroll
        for (int mt = 0; mt < 2; mt++)
#pragma unroll
            for (int nt = 0; nt < 8; nt++) {
                int row = m0 + wm * 32 + mt * 16 + lr;
                int col = n0 + wn * 64 + nt * 8 + lc2;
                if (C16) {
                    *(uint32_t*)(C16 + (size_t)row * N + col) = pack_h2(acc[mt][nt][0], acc[mt][nt][1]);
                    *(uint32_t*)(C16 + (size_t)(row + 8) * N + col) = pack_h2(acc[mt][nt][2], acc[mt][nt][3]);
                } else if (resid) {
                    float ga = gamma[col], gb = gamma[col + 1];
                    float2 r0 = *(const float2*)(resid + (size_t)row * N + col);
                    float2 r1 = *(const float2*)(resid + (size_t)(row + 8) * N + col);
                    *(float2*)(Cf + (size_t)row * N + col) =
                        make_float2(fmaf(ga, acc[mt][nt][0], r0.x), fmaf(gb, acc[mt][nt][1], r0.y));
                    *(float2*)(Cf + (size_t)(row + 8) * N + col) =
                        make_float2(fmaf(ga, acc[mt][nt][2], r1.x), fmaf(gb, acc[mt][nt][3], r1.y));
                } else {
                    *(float2*)(Cf + (size_t)row * N + col) = make_float2(acc[mt][nt][0], acc[mt][nt][1]);
                    *(float2*)(Cf + (size_t)(row + 8) * N + col) = make_float2(acc[mt][nt][2], acc[mt][nt][3]);
                }
            }
    }
}

// generic dense GEMM (used for Wo)
__global__ void __launch_bounds__(256, 2) hgemm16(
    const __half* __restrict__ A, const __half* __restrict__ B,
    float* __restrict__ Cf, __half* __restrict__ C16,
    const float* __restrict__ resid, const float* __restrict__ gamma,
    const float* __restrict__ nw, float nsc,
    int K, int N) {
    extern __shared__ char dsm[];
    dense_core(A, B, Cf, C16, resid, gamma, nw, nsc, K, N,
               blockIdx.x << 7, blockIdx.y << 7, dsm);
}

// fused QKV: z selects weight/output/norm
__global__ void __launch_bounds__(256, 2) qkv_k(const float* __restrict__ qn,
                                                const float* __restrict__ kn) {
    extern __shared__ char dsm[];
    const __half* B;
    __half* C;
    const float* nw;
    float nsc;
    switch (blockIdx.z) {
        case 0: B = g_Wq16; C = g_q16; nw = qn; nsc = 0.125f; break;
        case 1: B = g_Wk16; C = g_k16; nw = kn; nsc = 1.0f; break;
        default: B = g_Wv16; C = g_v16; nw = nullptr; nsc = 1.0f; break;
    }
    dense_core(g_x16, B, nullptr, C, nullptr, nullptr, nw, nsc, Dd, Dd,
               blockIdx.x << 7, blockIdx.y << 7, dsm);
}

// ---------------- flash attention ----------------
__global__ void __launch_bounds__(256) fmha_k() {
    extern __shared__ __half sm[];
    const uint32_t sb = smem_u32(sm);
    const int z = blockIdx.y, b = z >> 4, h = z & 15;
    const int m0 = blockIdx.x << 7;
    const int tid = threadIdx.x, lane = tid & 31, wm = tid >> 5;
    const __half* Q = g_q16 + (size_t)b * Ss * Dd + h * HDd;
    const __half* Kp = g_k16 + (size_t)b * Ss * Dd + h * HDd;
    const __half* Vp = g_v16 + (size_t)b * Ss * Dd + h * HDd;

    {
#pragma unroll
        for (int i = 0; i < 4; i++) {
            int c = tid + (i << 8);
            int row = c >> 3, ch = (c & 7) << 3;
            CP16(sb + (uint32_t)(row * 72 + ch) * 2, Q + (size_t)(m0 + row) * Dd + ch);
        }
#pragma unroll
        for (int i = 0; i < 4; i++) {
            int c = tid + (i << 8);
            int row = c >> 3, ch = (c & 7) << 3;
            CP16(sb + (uint32_t)(FK0 + row * 72 + ch) * 2, Kp + (size_t)row * Dd + ch);
            CP16(sb + (uint32_t)(FV0 + row * 72 + ch) * 2, Vp + (size_t)row * Dd + ch);
        }
        CPCOMMIT();
    }
    uint32_t aq[4][4];
    float o_acc[8][4];
#pragma unroll
    for (int i = 0; i < 8; i++)
#pragma unroll
        for (int j = 0; j < 4; j++) o_acc[i][j] = 0.f;
    float m_prev0 = -1e30f, m_prev1 = -1e30f, l0 = 0.f, l1 = 0.f;

    for (int it = 0; it < 8; it++) {
        if (it < 7) {
            uint32_t kb = sb + (uint32_t)(FK0 + ((it + 1) & 1) * FKV) * 2;
            uint32_t vb = sb + (uint32_t)(FV0 + ((it + 1) & 1) * FKV) * 2;
            int s0 = (it + 1) << 7;
#pragma unroll
            for (int i = 0; i < 4; i++) {
                int c = tid + (i << 8);
                int row = c >> 3, ch = (c & 7) << 3;
                CP16(kb + (uint32_t)(row * 72 + ch) * 2, Kp + (size_t)(s0 + row) * Dd + ch);
                CP16(vb + (uint32_t)(row * 72 + ch) * 2, Vp + (size_t)(s0 + row) * Dd + ch);
            }
        }
        CPCOMMIT();
        CPWAIT1();
        __syncthreads();
        if (it == 0) {
#pragma unroll
            for (int kb = 0; kb < 4; kb++)
                ldm4(aq[kb], sb + (uint32_t)((wm * 16 + (lane & 15)) * 72 +
                                             kb * 16 + (lane >> 4) * 8) * 2);
        }
        const uint32_t kbase = sb + (uint32_t)(FK0 + (it & 1) * FKV) * 2;
        const uint32_t vbase = sb + (uint32_t)(FV0 + (it & 1) * FKV) * 2;
        float s_acc[16][4];
#pragma unroll
        for (int i = 0; i < 16; i++)
#pragma unroll
            for (int j = 0; j < 4; j++) s_acc[i][j] = 0.f;
#pragma unroll
        for (int kb = 0; kb < 4; kb++)
#pragma unroll
            for (int nb2 = 0; nb2 < 8; nb2++) {
                uint32_t bk[4];
                ldm4(bk, kbase + (uint32_t)((nb2 * 16 + ((lane >> 4) & 1) * 8 + (lane & 7)) * 72 +
                                            kb * 16 + ((lane >> 3) & 1) * 8) * 2);
                mma_f16(s_acc[nb2 * 2], aq[kb], bk);
                mma_f16(s_acc[nb2 * 2 + 1], aq[kb], bk + 2);
            }
        float mx0 = -1e30f, mx1 = -1e30f;
#pragma unroll
        for (int t = 0; t < 16; t++) {
            mx0 = fmaxf(mx0, fmaxf(s_acc[t][0], s_acc[t][1]));
            mx1 = fmaxf(mx1, fmaxf(s_acc[t][2], s_acc[t][3]));
        }
        mx0 = fmaxf(mx0, __shfl_xor_sync(0xffffffffu, mx0, 1));
        mx0 = fmaxf(mx0, __shfl_xor_sync(0xffffffffu, mx0, 2));
        mx1 = fmaxf(mx1, __shfl_xor_sync(0xffffffffu, mx1, 1));
        mx1 = fmaxf(mx1, __shfl_xor_sync(0xffffffffu, mx1, 2));
        float mn0 = fmaxf(m_prev0, mx0), mn1 = fmaxf(m_prev1, mx1);
        float sc0 = fexp(m_prev0 - mn0), sc1 = fexp(m_prev1 - mn1);
        m_prev0 = mn0; m_prev1 = mn1;
        float rs0 = 0.f, rs1 = 0.f;
#pragma unroll
        for (int t = 0; t < 16; t++) {
            s_acc[t][0] = fexp(s_acc[t][0] - mn0);
            s_acc[t][1] = fexp(s_acc[t][1] - mn0);
            s_acc[t][2] = fexp(s_acc[t][2] - mn1);
            s_acc[t][3] = fexp(s_acc[t][3] - mn1);
            rs0 += s_acc[t][0] + s_acc[t][1];
            rs1 += s_acc[t][2] + s_acc[t][3];
        }
        rs0 += __shfl_xor_sync(0xffffffffu, rs0, 1);
        rs0 += __shfl_xor_sync(0xffffffffu, rs0, 2);
        rs1 += __shfl_xor_sync(0xffffffffu, rs1, 1);
        rs1 += __shfl_xor_sync(0xffffffffu, rs1, 2);
        l0 = l0 * sc0 + rs0;
        l1 = l1 * sc1 + rs1;
#pragma unroll
        for (int ot = 0; ot < 8; ot++) {
            o_acc[ot][0] *= sc0; o_acc[ot][1] *= sc0;
            o_acc[ot][2] *= sc1; o_acc[ot][3] *= sc1;
        }
#pragma unroll
        for (int pb = 0; pb < 8; pb++) {
            uint32_t ap[4];
            ap[0] = pack_h2(s_acc[2 * pb][0], s_acc[2 * pb][1]);
            ap[1] = pack_h2(s_acc[2 * pb][2], s_acc[2 * pb][3]);
            ap[2] = pack_h2(s_acc[2 * pb + 1][0], s_acc[2 * pb + 1][1]);
            ap[3] = pack_h2(s_acc[2 * pb + 1][2], s_acc[2 * pb + 1][3]);
#pragma unroll
            for (int nb2 = 0; nb2 < 4; nb2++) {
                uint32_t bv[4];
                ldm4t(bv, vbase + (uint32_t)((pb * 16 + (lane & 7) + ((lane >> 3) & 1) * 8) * 72 +
                                             nb2 * 16 + (lane >> 4) * 8) * 2);
                mma_f16(o_acc[nb2 * 2], ap, bv);
                mma_f16(o_acc[nb2 * 2 + 1], ap, bv + 2);
            }
        }
        __syncthreads();
    }
    const float inv0 = 1.f / l0, inv1 = 1.f / l1;
    __half* O = g_o16 + (size_t)b * Ss * Dd + h * HDd;
    const int r = m0 + wm * 16 + (lane >> 2), c2 = (lane & 3) * 2;
#pragma unroll
    for (int ot = 0; ot < 8; ot++) {
        int col = ot * 8 + c2;
        *(uint32_t*)(O + (size_t)r * Dd + col) =
            pack_h2(o_acc[ot][0] * inv0, o_acc[ot][1] * inv0);
        *(uint32_t*)(O + (size_t)(r + 8) * Dd + col) =
            pack_h2(o_acc[ot][2] * inv1, o_acc[ot][3] * inv1);
    }
}

// ---------------- MoE gate/up k64, 3-stage + SiLU -> fp16 h ----------------
__global__ void __launch_bounds__(256) moe_gu16() {
    extern __shared__ __half sm[];
    __shared__ int toks[128];
    const int e = blockIdx.z;
    const int cnt = g_cnt[e];
    const int m0 = blockIdx.x << 7;
    if (m0 >= cnt) return;
    const int n0 = blockIdx.y << 7;
    const uint32_t sb = smem_u32(sm);
    const int tid = threadIdx.x, lane = tid & 31, wid = tid >> 5;
    const int wm = wid & 3, wn = wid >> 2;
    if (tid < 128) toks[tid] = g_assign[e * CAP + min(m0 + tid, cnt - 1)];
    __syncthreads();

    const size_t eo = (size_t)e * Dd * Ff;
    const __half* G = g_Wg16 + eo;
    const __half* U = g_Wu16 + eo;

    float ag[2][8][4], au[2][8][4];
#pragma unroll
    for (int a = 0; a < 2; a++)
#pragma unroll
        for (int c = 0; c < 8; c++)
#pragma unroll
            for (int d = 0; d < 4; d++) { ag[a][c][d] = 0.f; au[a][c][d] = 0.f; }

    const int ra = tid >> 3, ca = (tid & 7) << 3;
    const int rb = tid >> 4, cb = (tid & 15) << 3;

    auto issue = [&](int stg) {
        uint32_t base = sb + (uint32_t)(stg % 3) * STEg * 2;
        int k0 = stg << 6;
#pragma unroll
        for (int i = 0; i < 4; i++)
            CP16(base + (uint32_t)((ra + i * 32) * RS + ca) * 2,
                 g_xt16 + (size_t)toks[ra + i * 32] * Dd + k0 + ca);
#pragma unroll
        for (int i = 0; i < 4; i++) {
            CP16(base + (uint32_t)(OFG + (rb + i * 16) * RSB + cb) * 2,
                 G + (size_t)(k0 + rb + i * 16) * Ff + n0 + cb);
            CP16(base + (uint32_t)(OFU + (rb + i * 16) * RSB + cb) * 2,
                 U + (size_t)(k0 + rb + i * 16) * Ff + n0 + cb);
        }
    };
    issue(0); CPCOMMIT();
    issue(1); CPCOMMIT();

    const int nb = Dd >> 6;  // 16
    for (int it = 0; it < nb; it++) {
        if (it + 2 < nb) issue(it + 2);
        CPCOMMIT();
        CPWAIT2();
        __syncthreads();
        uint32_t base = sb + (uint32_t)(it % 3) * STEg * 2;
#pragma unroll
        for (int ks = 0; ks < 4; ks++) {
            uint32_t a[2][4];
#pragma unroll
            for (int mt = 0; mt < 2; mt++)
                ldm4(a[mt], base + (uint32_t)((wm * 32 + mt * 16 + (lane & 15)) * RS +
                                              ks * 16 + (lane >> 4) * 8) * 2);
            uint32_t roff = (uint32_t)((ks * 16 + (lane & 7) + ((lane >> 3) & 1) * 8) * RSB) * 2;
            uint32_t coff[4];
#pragma unroll
            for (int bt = 0; bt < 4; bt++)
                coff[bt] = (uint32_t)(wn * 64 + bt * 16 + (lane >> 4) * 8) * 2;
            {
                uint32_t bg[4][4];
#pragma unroll
                for (int bt = 0; bt < 4; bt++)
                    ldm4t(bg[bt], base + OFG * 2 + roff + coff[bt]);
#pragma unroll
                for (int mt = 0; mt < 2; mt++)
#pragma unroll
                    for (int nt = 0; nt < 8; nt++)
                        mma_f16(ag[mt][nt], a[mt], &bg[nt >> 1][(nt & 1) * 2]);
            }
            {
                uint32_t bu[4][4];
#pragma unroll
                for (int bt = 0; bt < 4; bt++)
                    ldm4t(bu[bt], base + OFU * 2 + roff + coff[bt]);
#pragma unroll
                for (int mt = 0; mt < 2; mt++)
#pragma unroll
                    for (int nt = 0; nt < 8; nt++)
                        mma_f16(au[mt][nt], a[mt], &bu[nt >> 1][(nt & 1) * 2]);
            }
        }
        __syncthreads();
    }
    const int lr = lane >> 2, lc2 = (lane & 3) * 2;
#pragma unroll
    for (int mt = 0; mt < 2; mt++)
#pragma unroll
        for (int nt = 0; nt < 8; nt++) {
            int r = m0 + wm * 32 + mt * 16 + lr;
            int col = n0 + wn * 64 + nt * 8 + lc2;
#pragma unroll
            for (int half = 0; half < 2; half++) {
                int rr = r + half * 8;
                if (rr < cnt) {
                    float gv0 = ag[mt][nt][half * 2], gv1 = ag[mt][nt][half * 2 + 1];
                    float uv0 = au[mt][nt][half * 2], uv1 = au[mt][nt][half * 2 + 1];
                    float v0 = gv0 * frcp(1.f + fexp(-gv0)) * uv0;
                    float v1 = gv1 * frcp(1.f + fexp(-gv1)) * uv1;
                    *(uint32_t*)(g_h16 + ((size_t)e * CAP + rr) * Ff + col) = pack_h2(v0, v1);
                }
            }
        }
}

// ---------------- MoE down k64 -> fp16 moeout (slot rows) ----------------
__global__ void __launch_bounds__(256, 2) moe_down16() {
    extern __shared__ __half sm[];
    const int e = blockIdx.z;
    const int cnt = g_cnt[e];
    const int m0 = blockIdx.x << 7;
    if (m0 >= cnt) return;
    const int n0 = blockIdx.y << 7;
    const uint32_t sb = smem_u32(sm);
    const int tid = threadIdx.x, lane = tid & 31, wid = tid >> 5;
    const int wm = wid & 3, wn = wid >> 2;
    const int cm1 = cnt - 1;

    const __half* A = g_h16 + (size_t)e * CAP * Ff;
    const __half* B = g_Wd16 + (size_t)e * Ff * Dd;

    float acc[2][8][4];
#pragma unroll
    for (int a = 0; a < 2; a++)
#pragma unroll
        for (int c = 0; c < 8; c++)
#pragma unroll
            for (int d = 0; d < 4; d++) acc[a][c][d] = 0.f;

    const int ra = tid >> 3, ca = (tid & 7) << 3;
    const int rb = tid >> 4, cb = (tid & 15) << 3;
    {
        uint32_t base = sb;
#pragma unroll
        for (int i = 0; i < 4; i++)
            CP16(base + (uint32_t)((ra + i * 32) * RS + ca) * 2,
                 A + (size_t)min(m0 + ra + i * 32, cm1) * Ff + ca);
#pragma unroll
        for (int i = 0; i < 4; i++)
            CP16(base + (uint32_t)(OFB + (rb + i * 16) * RSB + cb) * 2,
                 B + (size_t)(rb + i * 16) * Dd + n0 + cb);
        CPCOMMIT();
    }
    const int nb = Ff >> 6;
    for (int it = 0; it < nb; it++) {
        if (it + 1 < nb) {
            uint32_t base = sb + (uint32_t)((it + 1) & 1) * STEd * 2;
            int k0 = (it + 1) << 6;
#pragma unroll
            for (int i = 0; i < 4; i++)
                CP16(base + (uint32_t)((ra + i * 32) * RS + ca) * 2,
                     A + (size_t)min(m0 + ra + i * 32, cm1) * Ff + k0 + ca);
#pragma unroll
            for (int i = 0; i < 4; i++)
                CP16(base + (uint32_t)(OFB + (rb + i * 16) * RSB + cb) * 2,
                     B + (size_t)(k0 + rb + i * 16) * Dd + n0 + cb);
        }
        CPCOMMIT();
        CPWAIT1();
        __syncthreads();
        uint32_t base = sb + (uint32_t)(it & 1) * STEd * 2;
#pragma unroll
        for (int ks = 0; ks < 4; ks++) {
            uint32_t a[2][4];
#pragma unroll
            for (int mt = 0; mt < 2; mt++)
                ldm4(a[mt], base + (uint32_t)((wm * 32 + mt * 16 + (lane & 15)) * RS +
                                              ks * 16 + (lane >> 4) * 8) * 2);
            uint32_t bq[4][4];
#pragma unroll
            for (int bt = 0; bt < 4; bt++)
                ldm4t(bq[bt], base + (uint32_t)(OFB +
                                                (ks * 16 + (lane & 7) + ((lane >> 3) & 1) * 8) * RSB +
                                                wn * 64 + bt * 16 + (lane >> 4) * 8) * 2);
#pragma unroll
            for (int mt = 0; mt < 2; mt++)
#pragma unroll
                for (int nt = 0; nt < 8; nt++)
                    mma_f16(acc[mt][nt], a[mt], &bq[nt >> 1][(nt & 1) * 2]);
        }
        __syncthreads();
    }
    const int lr = lane >> 2, lc2 = (lane & 3) * 2;
#pragma unroll
    for (int mt = 0; mt < 2; mt++)
#pragma unroll
        for (int half = 0; half < 2; half++) {
            int r = m0 + wm * 32 + mt * 16 + lr + half * 8;
            if (r < cnt) {
                __half* op = g_moeout16 + ((size_t)e * CAP + r) * Dd;
#pragma unroll
                for (int nt = 0; nt < 8; nt++) {
                    int col = n0 + wn * 64 + nt * 8 + lc2;
                    *(uint32_t*)(op + col) = pack_h2(acc[mt][nt][half * 2],
                                                     acc[mt][nt][half * 2 + 1]);
                }
            }
        }
}

// ---------------- final gather (fp16 moeout, 8 elems/thread) + counter reset ----------------
__global__ void final_k(float* __restrict__ out) {
    const size_t i8 = ((size_t)blockIdx.x * 256 + threadIdx.x) * 8;
#pragma unroll
    for (int half = 0; half < 2; half++) {
        const size_t i4 = i8 + half * 4;
        const int t = (int)(i4 >> 10);
        const int c = (int)(i4 & 1023);
        const int s0 = g_slotid[t * 2 + 0], s1 = g_slotid[t * 2 + 1];
        const float w0 = g_topw[t * 2 + 0], w1 = g_topw[t * 2 + 1];
        float4 hv = *(const float4*)(g_hidden + i4);
        uint2 m0p = *(const uint2*)(g_moeout16 + (size_t)s0 * Dd + c);
        uint2 m1p = *(const uint2*)(g_moeout16 + (size_t)s1 * Dd + c);
        __half2 m0a = *(__half2*)&m0p.x, m0b = *(__half2*)&m0p.y;
        __half2 m1a = *(__half2*)&m1p.x, m1b = *(__half2*)&m1p.y;
        hv.x += w0 * __half2float(m0a.x) + w1 * __half2float(m1a.x);
        hv.y += w0 * __half2float(m0a.y) + w1 * __half2float(m1a.y);
        hv.z += w0 * __half2float(m0b.x) + w1 * __half2float(m1b.x);
        hv.w += w0 * __half2float(m0b.y) + w1 * __half2float(m1b.y);
        *(float4*)(out + i4) = hv;
    }
    // reset expert counters for the next graph replay (globals start zeroed at load)
    if (blockIdx.x == 0 && threadIdx.x < Ee) g_cnt[threadIdx.x] = 0;
}

// ---------------- launch ----------------
extern "C" void kernel_launch(void* const* d_in, const int* in_sizes, int n_in,
                              void* d_out, int out_size) {
    (void)in_sizes; (void)n_in;
    const float* hs    = (const float*)d_in[0];
    const float* ln1   = (const float*)d_in[1];
    const float* ln2   = (const float*)d_in[2];
    const float* Wq    = (const float*)d_in[3];
    const float* Wk    = (const float*)d_in[4];
    const float* Wv    = (const float*)d_in[5];
    const float* Wo    = (const float*)d_in[6];
    const float* qn    = (const float*)d_in[7];
    const float* kn    = (const float*)d_in[8];
    const float* gamma = (const float*)d_in[9];
    const float* gw    = (const float*)d_in[10];
    const float* Wg    = (const float*)d_in[11];
    const float* Wu    = (const float*)d_in[12];
    const float* Wd    = (const float*)d_in[13];
    float* out = (float*)d_out;

    float* p_hidden;
    cudaGetSymbolAddress((void**)&p_hidden, g_hidden);

    __half *wg16, *wu16, *wd16, *wo16, *x16, *o16, *xt16;
    cudaGetSymbolAddress((void**)&wg16, g_Wg16);
    cudaGetSymbolAddress((void**)&wu16, g_Wu16);
    cudaGetSymbolAddress((void**)&wd16, g_Wd16);
    cudaGetSymbolAddress((void**)&wo16, g_Wo16);
    cudaGetSymbolAddress((void**)&x16, g_x16);
    cudaGetSymbolAddress((void**)&o16, g_o16);
    cudaGetSymbolAddress((void**)&xt16, g_xt16);

    cudaFuncSetAttribute(hgemm16, cudaFuncAttributeMaxDynamicSharedMemorySize, SMEMd);
    cudaFuncSetAttribute(qkv_k, cudaFuncAttributeMaxDynamicSharedMemorySize, SMEMd);
    cudaFuncSetAttribute(moe_down16, cudaFuncAttributeMaxDynamicSharedMemorySize, SMEMd);
    cudaFuncSetAttribute(moe_gu16, cudaFuncAttributeMaxDynamicSharedMemorySize, SMEMg3);
    cudaFuncSetAttribute(fmha_k, cudaFuncAttributeMaxDynamicSharedMemorySize, SMEMf);

    // side streams + events (created once; reused across captures)
    static cudaStream_t s2 = 0, s3 = 0;
    static cudaEvent_t evF = 0, evJ = 0, evJ3 = 0;
    static int sinit = 0;
    if (!sinit) {
        if (cudaStreamCreateWithFlags(&s2, cudaStreamNonBlocking) != cudaSuccess) s2 = 0;
        if (cudaStreamCreateWithFlags(&s3, cudaStreamNonBlocking) != cudaSuccess) s3 = 0;
        cudaEventCreateWithFlags(&evF, cudaEventDisableTiming);
        cudaEventCreateWithFlags(&evJ, cudaEventDisableTiming);
        cudaEventCreateWithFlags(&evJ3, cudaEventDisableTiming);
        sinit = 1;
    }

    // fork FIRST: big MoE weight converts on s2; small converts on s3
    cudaEventRecord(evF, 0);
    cudaStreamWaitEvent(s2, evF, 0);
    cudaStreamWaitEvent(s3, evF, 0);
    wconv_k<<<(int)((size_t)Ee * Dd * Ff / 2048), 256, 0, s2>>>(Wg, wg16);
    wconv_k<<<(int)((size_t)Ee * Dd * Ff / 2048), 256, 0, s2>>>(Wu, wu16);
    wconv_k<<<(int)((size_t)Ee * Ff * Dd / 2048), 256, 0, s2>>>(Wd, wd16);
    cudaEventRecord(evJ, s2);
    wconv4_k<<<dim3(Dd * Dd / 2048, 1, 4), 256, 0, s3>>>(Wq, Wk, Wv, Wo);
    cudaEventRecord(evJ3, s3);

    // --- attention branch ---
    rmsnorm_h<<<Tt, 256>>>(hs, ln1, x16);
    cudaStreamWaitEvent(0, evJ3, 0);   // QKV/Wo fp16 weights ready
    qkv_k<<<dim3(32, 8, 3), 256, SMEMd>>>(qn, kn);
    fmha_k<<<dim3(8, 64), 256, SMEMf>>>();
    hgemm16<<<dim3(32, 8), 256, SMEMd>>>(o16, wo16, p_hidden, nullptr, hs, gamma, nullptr, 1.f, Dd, Dd);

    // --- MoE branch (serial, full-z launches: best measured packing) ---
    int write_logits = (out_size >= Tt * Dd + Tt * Ee) ? 1 : 0;
    rmsnorm_router_k<<<Tt, 256>>>(p_hidden, ln2, gw, xt16, out + (size_t)Tt * Dd, write_logits);
    cudaStreamWaitEvent(0, evJ, 0);   // MoE weights ready
    moe_gu16<<<dim3(CAP / 128, Ff / 128, Ee), 256, SMEMg3>>>();
    moe_down16<<<dim3(CAP / 128, Dd / 128, Ee), 256, SMEMd>>>();
    final_k<<<Tt * Dd / 2048, 256>>>(out);
}

// round 17
// speedup vs baseline: 1.0022x; 1.0022x over previous
#include <cuda_runtime.h>
#include <cuda_fp16.h>
#include <math.h>
#include <stdint.h>

// ---------------- constants ----------------
#define Bb 4
#define Ss 1024
#define Tt 4096
#define Dd 1024
#define Hh 16
#define HDd 64
#define Ee 8
#define Ff 4096
#define CAP 4096
#define EPSf 1e-6f

#define RS  72             // A-tile smem row stride (halves), k64
#define RSB 136            // B-tile ([K][N]) smem row stride (halves)

// k64 stage layouts (halves)
#define OFB  9216          // dense/down: A[128][72] then B[64][136]
#define STEd 17920
#define OFG  9216          // gu: A[128][72], G[64][136], U[64][136]
#define OFU  17920
#define STEg 26624

#define SMEMd (2 * STEd * 2)    // 71680 B (2-stage, 2 CTA/SM)
#define SMEMg3 (3 * STEg * 2)   // 159744 B (3-stage, 1 CTA/SM)

// fmha smem (halves): Q[128][72], K0,V0,K1,V1 each [128][72]
#define FK0 9216
#define FV0 18432
#define FKV 18432
#define SMEMf (46080 * 2)

// ---------------- scratch ----------------
__device__ __align__(256) float g_hidden[(size_t)Tt * Dd];
__device__ __align__(256) __half g_moeout16[(size_t)Ee * CAP * Dd];
__device__ float g_topw[Tt * 2];
__device__ int   g_slotid[Tt * 2];
__device__ int   g_cnt[Ee];
__device__ int   g_assign[Ee * CAP];

__device__ __align__(256) __half g_x16[(size_t)Tt * Dd];
__device__ __align__(256) __half g_q16[(size_t)Tt * Dd];
__device__ __align__(256) __half g_k16[(size_t)Tt * Dd];
__device__ __align__(256) __half g_v16[(size_t)Tt * Dd];
__device__ __align__(256) __half g_o16[(size_t)Tt * Dd];
__device__ __align__(256) __half g_xt16[(size_t)Tt * Dd];
__device__ __align__(256) __half g_h16[(size_t)Ee * CAP * Ff];

// fp16 weights, ORIGINAL layout [K][N]
__device__ __align__(256) __half g_Wg16[(size_t)Ee * Dd * Ff];
__device__ __align__(256) __half g_Wu16[(size_t)Ee * Dd * Ff];
__device__ __align__(256) __half g_Wd16[(size_t)Ee * Ff * Dd];
__device__ __align__(256) __half g_Wq16[(size_t)Dd * Dd];
__device__ __align__(256) __half g_Wk16[(size_t)Dd * Dd];
__device__ __align__(256) __half g_Wv16[(size_t)Dd * Dd];
__device__ __align__(256) __half g_Wo16[(size_t)Dd * Dd];

// ---------------- helpers ----------------
__device__ __forceinline__ float warp_red_sum(float v) {
#pragma unroll
    for (int o = 16; o; o >>= 1) v += __shfl_xor_sync(0xffffffffu, v, o);
    return v;
}
__device__ __forceinline__ uint32_t smem_u32(const void* p) {
    uint32_t a;
    asm("{ .reg .u64 t; cvta.to.shared.u64 t, %1; cvt.u32.u64 %0, t; }" : "=r"(a) : "l"(p));
    return a;
}
#define CP16(sm, gp) \
    asm volatile("cp.async.ca.shared.global [%0], [%1], 16;" :: "r"(sm), "l"(gp))
#define CPCOMMIT() asm volatile("cp.async.commit_group;")
#define CPWAIT1() asm volatile("cp.async.wait_group 1;")
#define CPWAIT2() asm volatile("cp.async.wait_group 2;")

__device__ __forceinline__ void ldm4(uint32_t* r, uint32_t addr) {
    asm volatile("ldmatrix.sync.aligned.m8n8.x4.shared.b16 {%0,%1,%2,%3}, [%4];"
                 : "=r"(r[0]), "=r"(r[1]), "=r"(r[2]), "=r"(r[3]) : "r"(addr));
}
__device__ __forceinline__ void ldm4t(uint32_t* r, uint32_t addr) {
    asm volatile("ldmatrix.sync.aligned.m8n8.x4.trans.shared.b16 {%0,%1,%2,%3}, [%4];"
                 : "=r"(r[0]), "=r"(r[1]), "=r"(r[2]), "=r"(r[3]) : "r"(addr));
}
__device__ __forceinline__ void mma_f16(float* c, const uint32_t* a, const uint32_t* b) {
    asm volatile(
        "mma.sync.aligned.m16n8k16.row.col.f32.f16.f16.f32 "
        "{%0,%1,%2,%3},{%4,%5,%6,%7},{%8,%9},{%0,%1,%2,%3};"
        : "+f"(c[0]), "+f"(c[1]), "+f"(c[2]), "+f"(c[3])
        : "r"(a[0]), "r"(a[1]), "r"(a[2]), "r"(a[3]), "r"(b[0]), "r"(b[1]));
}
__device__ __forceinline__ uint32_t pack_h2(float a, float b) {
    __half2 h; h.x = __float2half_rn(a); h.y = __float2half_rn(b);
    return *(uint32_t*)&h;
}
// fast exp on FMA pipe (rel err ~4e-5)
__device__ __forceinline__ float fexp(float x) {
    x = fminf(fmaxf(x, -60.f), 60.f);
    float z = x * 1.442695041f;
    float j = z + 12582912.f;
    int i = __float_as_int(j) - 0x4b400000;
    float f = z - (j - 12582912.f);
    float p = fmaf(f, 0.009618129f, 0.055504110f);
    p = fmaf(f, p, 0.240226507f);
    p = fmaf(f, p, 0.693147181f);
    p = fmaf(f, p, 1.0f);
    return __int_as_float(__float_as_int(p) + (i << 23));
}
__device__ __forceinline__ float frcp(float d) {
    float r = __uint_as_float(0x7ef311c3u - __float_as_uint(d));
    r = r * (2.0f - d * r);
    r = r * (2.0f - d * r);
    r = r * (2.0f - d * r);
    return r;
}

// ---------------- streaming weight convert fp32 -> fp16 (8 elems/thread) ----------------
__global__ void wconv_k(const float* __restrict__ in, __half* __restrict__ o) {
    const size_t i = ((size_t)blockIdx.x * 256 + threadIdx.x) * 8;
    float4 a = *(const float4*)(in + i);
    float4 b = *(const float4*)(in + i + 4);
    uint4 p;
    p.x = pack_h2(a.x, a.y);
    p.y = pack_h2(a.z, a.w);
    p.z = pack_h2(b.x, b.y);
    p.w = pack_h2(b.z, b.w);
    *(uint4*)(o + i) = p;
}

// batched small converts: z selects (Wq,Wk,Wv,Wo)
__global__ void wconv4_k(const float* __restrict__ wq, const float* __restrict__ wk,
                         const float* __restrict__ wv, const float* __restrict__ wo) {
    const float* in;
    __half* o;
    switch (blockIdx.z) {
        case 0: in = wq; o = g_Wq16; break;
        case 1: in = wk; o = g_Wk16; break;
        case 2: in = wv; o = g_Wv16; break;
        default: in = wo; o = g_Wo16; break;
    }
    const size_t i = ((size_t)blockIdx.x * 256 + threadIdx.x) * 8;
    float4 a = *(const float4*)(in + i);
    float4 b = *(const float4*)(in + i + 4);
    uint4 p;
    p.x = pack_h2(a.x, a.y);
    p.y = pack_h2(a.z, a.w);
    p.z = pack_h2(b.x, b.y);
    p.w = pack_h2(b.z, b.w);
    *(uint4*)(o + i) = p;
}

// ---------------- RMSNorm -> fp16 ----------------
__global__ void rmsnorm_h(const float* __restrict__ in, const float* __restrict__ w,
                          __half* __restrict__ o16) {
    const int t = blockIdx.x;
    const float* x = in + (size_t)t * Dd;
    float ss = 0.f;
    float v4[4];
#pragma unroll
    for (int j = 0; j < 4; j++) {
        float v = x[threadIdx.x + j * 256];
        v4[j] = v;
        ss = fmaf(v, v, ss);
    }
    __shared__ float red[8];
    __shared__ float sres;
    float ws = warp_red_sum(ss);
    if ((threadIdx.x & 31) == 0) red[threadIdx.x >> 5] = ws;
    __syncthreads();
    if (threadIdx.x == 0) {
        float s = 0.f;
        for (int i = 0; i < 8; i++) s += red[i];
        sres = rsqrtf(s * (1.f / Dd) + EPSf);
    }
    __syncthreads();
    const float r = sres;
#pragma unroll
    for (int j = 0; j < 4; j++) {
        int i = threadIdx.x + j * 256;
        o16[(size_t)t * Dd + i] = __float2half_rn(v4[j] * r * w[i]);
    }
}

// ---------------- fused RMSNorm + router + slot assignment (block = token) ----------------
__global__ void rmsnorm_router_k(const float* __restrict__ in, const float* __restrict__ w,
                                 const float* __restrict__ Gw, __half* __restrict__ o16,
                                 float* __restrict__ logits_out, int write_logits) {
    const int t = blockIdx.x;
    const int tid = threadIdx.x;
    const float* x = in + (size_t)t * Dd;
    float ss = 0.f;
    float v4[4];
#pragma unroll
    for (int j = 0; j < 4; j++) {
        float v = x[tid + j * 256];
        v4[j] = v;
        ss = fmaf(v, v, ss);
    }
    __shared__ float red[8];
    __shared__ float red8[8][8];
    __shared__ float lgs[8];
    __shared__ float sres;
    float ws = warp_red_sum(ss);
    if ((tid & 31) == 0) red[tid >> 5] = ws;
    __syncthreads();
    if (tid == 0) {
        float s = 0.f;
        for (int i = 0; i < 8; i++) s += red[i];
        sres = rsqrtf(s * (1.f / Dd) + EPSf);
    }
    __syncthreads();
    const float r = sres;
    float s[8];
#pragma unroll
    for (int e = 0; e < 8; e++) s[e] = 0.f;
#pragma unroll
    for (int j = 0; j < 4; j++) {
        int i = tid + j * 256;
        float v = v4[j] * r * w[i];
        o16[(size_t)t * Dd + i] = __float2half_rn(v);
        float4 g0 = *(const float4*)(Gw + (size_t)i * 8);
        float4 g1 = *(const float4*)(Gw + (size_t)i * 8 + 4);
        s[0] = fmaf(v, g0.x, s[0]); s[1] = fmaf(v, g0.y, s[1]);
        s[2] = fmaf(v, g0.z, s[2]); s[3] = fmaf(v, g0.w, s[3]);
        s[4] = fmaf(v, g1.x, s[4]); s[5] = fmaf(v, g1.y, s[5]);
        s[6] = fmaf(v, g1.z, s[6]); s[7] = fmaf(v, g1.w, s[7]);
    }
#pragma unroll
    for (int e = 0; e < 8; e++) s[e] = warp_red_sum(s[e]);
    if ((tid & 31) == 0) {
#pragma unroll
        for (int e = 0; e < 8; e++) red8[tid >> 5][e] = s[e];
    }
    __syncthreads();
    if (tid == 0) {
        float lg[8];
#pragma unroll
        for (int e = 0; e < 8; e++) {
            float a = 0.f;
            for (int wdx = 0; wdx < 8; wdx++) a += red8[wdx][e];
            lg[e] = a;
            lgs[e] = a;
        }
        float mx = lg[0];
#pragma unroll
        for (int e = 1; e < 8; e++) mx = fmaxf(mx, lg[e]);
        float p[8];
        float sum = 0.f;
#pragma unroll
        for (int e = 0; e < 8; e++) { p[e] = __expf(lg[e] - mx); sum += p[e]; }
        int i0 = 0;
#pragma unroll
        for (int e = 1; e < 8; e++) if (p[e] > p[i0]) i0 = e;
        int i1 = (i0 == 0) ? 1 : 0;
#pragma unroll
        for (int e = 0; e < 8; e++) if (e != i0 && p[e] > p[i1]) i1 = e;
        float v0 = p[i0] / sum, v1 = p[i1] / sum;
        float inv = 1.f / (v0 + v1);
        g_topw[t * 2 + 0] = v0 * inv;
        g_topw[t * 2 + 1] = v1 * inv;
        int pos0 = atomicAdd(&g_cnt[i0], 1);
        g_assign[i0 * CAP + pos0] = t;
        g_slotid[t * 2 + 0] = i0 * CAP + pos0;
        int pos1 = atomicAdd(&g_cnt[i1], 1);
        g_assign[i1 * CAP + pos1] = t;
        g_slotid[t * 2 + 1] = i1 * CAP + pos1;
    }
    __syncthreads();
    if (write_logits && tid < 8) logits_out[(size_t)t * 8 + tid] = lgs[tid];
}

// ---------------- shared dense-GEMM core (k64, 2-stage) ----------------
__device__ __forceinline__ void dense_core(
    const __half* __restrict__ A, const __half* __restrict__ B,
    float* __restrict__ Cf, __half* __restrict__ C16,
    const float* __restrict__ resid, const float* __restrict__ gamma,
    const float* __restrict__ nw, float nsc,
    int K, int N, int m0, int n0, char* smp) {
    const uint32_t sb = smem_u32(smp);
    const int tid = threadIdx.x, lane = tid & 31, wid = tid >> 5;
    const int wm = wid & 3, wn = wid >> 2;

    float acc[2][8][4];
#pragma unroll
    for (int a = 0; a < 2; a++)
#pragma unroll
        for (int b = 0; b < 8; b++)
#pragma unroll
            for (int c = 0; c < 4; c++) acc[a][b][c] = 0.f;

    const int ra = tid >> 3, ca = (tid & 7) << 3;
    const int rb = tid >> 4, cb = (tid & 15) << 3;
    {
        uint32_t base = sb;
#pragma unroll
        for (int i = 0; i < 4; i++)
            CP16(base + (uint32_t)((ra + i * 32) * RS + ca) * 2,
                 A + (size_t)(m0 + ra + i * 32) * K + ca);
#pragma unroll
        for (int i = 0; i < 4; i++)
            CP16(base + (uint32_t)(OFB + (rb + i * 16) * RSB + cb) * 2,
                 B + (size_t)(rb + i * 16) * N + n0 + cb);
        CPCOMMIT();
    }
    const int nb = K >> 6;
    for (int it = 0; it < nb; it++) {
        if (it + 1 < nb) {
            uint32_t base = sb + (uint32_t)((it + 1) & 1) * STEd * 2;
            int k0 = (it + 1) << 6;
#pragma unroll
            for (int i = 0; i < 4; i++)
                CP16(base + (uint32_t)((ra + i * 32) * RS + ca) * 2,
                     A + (size_t)(m0 + ra + i * 32) * K + k0 + ca);
#pragma unroll
            for (int i = 0; i < 4; i++)
                CP16(base + (uint32_t)(OFB + (rb + i * 16) * RSB + cb) * 2,
                     B + (size_t)(k0 + rb + i * 16) * N + n0 + cb);
        }
        CPCOMMIT();
        CPWAIT1();
        __syncthreads();
        uint32_t base = sb + (uint32_t)(it & 1) * STEd * 2;
#pragma unroll
        for (int ks = 0; ks < 4; ks++) {
            uint32_t a[2][4];
#pragma unroll
            for (int mt = 0; mt < 2; mt++)
                ldm4(a[mt], base + (uint32_t)((wm * 32 + mt * 16 + (lane & 15)) * RS +
                                              ks * 16 + (lane >> 4) * 8) * 2);
            uint32_t bq[4][4];
#pragma unroll
            for (int bt = 0; bt < 4; bt++)
                ldm4t(bq[bt], base + (uint32_t)(OFB +
                                                (ks * 16 + (lane & 7) + ((lane >> 3) & 1) * 8) * RSB +
                                                wn * 64 + bt * 16 + (lane >> 4) * 8) * 2);
#pragma unroll
            for (int mt = 0; mt < 2; mt++)
#pragma unroll
                for (int nt = 0; nt < 8; nt++)
                    mma_f16(acc[mt][nt], a[mt], &bq[nt >> 1][(nt & 1) * 2]);
        }
        __syncthreads();
    }
    const int lr = lane >> 2, lc2 = (lane & 3) * 2;
    if (C16 && nw) {
#pragma unroll
        for (int mt = 0; mt < 2; mt++)
#pragma unroll
            for (int half = 0; half < 2; half++) {
                float ss = 0.f;
#pragma unroll
                for (int nt = 0; nt < 8; nt++) {
                    float a0 = acc[mt][nt][half * 2], a1 = acc[mt][nt][half * 2 + 1];
                    ss = fmaf(a0, a0, fmaf(a1, a1, ss));
                }
                ss += __shfl_xor_sync(0xffffffffu, ss, 1);
                ss += __shfl_xor_sync(0xffffffffu, ss, 2);
                float r = rsqrtf(ss * (1.f / HDd) + EPSf) * nsc;
                int row = m0 + wm * 32 + mt * 16 + lr + half * 8;
#pragma unroll
                for (int nt = 0; nt < 8; nt++) {
                    int wcol = nt * 8 + lc2;
                    int col = n0 + wn * 64 + wcol;
                    *(uint32_t*)(C16 + (size_t)row * N + col) =
                        pack_h2(acc[mt][nt][half * 2] * r * nw[wcol],
                                acc[mt][nt][half * 2 + 1] * r * nw[wcol + 1]);
                }
            }
    } else {
#pragma unroll
        for (int mt = 0; mt < 2; mt++)
#pragma unroll
            for (int nt = 0; nt < 8; nt++) {
                int row = m0 + wm * 32 + mt * 16 + lr;
                int col = n0 + wn * 64 + nt * 8 + lc2;
                if (C16) {
                    *(uint32_t*)(C16 + (size_t)row * N + col) = pack_h2(acc[mt][nt][0], acc[mt][nt][1]);
                    *(uint32_t*)(C16 + (size_t)(row + 8) * N + col) = pack_h2(acc[mt][nt][2], acc[mt][nt][3]);
                } else if (resid) {
                    float ga = gamma[col], gb = gamma[col + 1];
                    float2 r0 = *(const float2*)(resid + (size_t)row * N + col);
                    float2 r1 = *(const float2*)(resid + (size_t)(row + 8) * N + col);
                    *(float2*)(Cf + (size_t)row * N + col) =
                        make_float2(fmaf(ga, acc[mt][nt][0], r0.x), fmaf(gb, acc[mt][nt][1], r0.y));
                    *(float2*)(Cf + (size_t)(row + 8) * N + col) =
                        make_float2(fmaf(ga, acc[mt][nt][2], r1.x), fmaf(gb, acc[mt][nt][3], r1.y));
                } else {
                    *(float2*)(Cf + (size_t)row * N + col) = make_float2(acc[mt][nt][0], acc[mt][nt][1]);
                    *(float2*)(Cf + (size_t)(row + 8) * N + col) = make_float2(acc[mt][nt][2], acc[mt][nt][3]);
                }
            }
    }
}

// generic dense GEMM (used for Wo)
__global__ void __launch_bounds__(256, 2) hgemm16(
    const __half* __restrict__ A, const __half* __restrict__ B,
    float* __restrict__ Cf, __half* __restrict__ C16,
    const float* __restrict__ resid, const float* __restrict__ gamma,
    const float* __restrict__ nw, float nsc,
    int K, int N) {
    extern __shared__ char dsm[];
    dense_core(A, B, Cf, C16, resid, gamma, nw, nsc, K, N,
               blockIdx.x << 7, blockIdx.y << 7, dsm);
}

// fused QKV: z selects weight/output/norm
__global__ void __launch_bounds__(256, 2) qkv_k(const float* __restrict__ qn,
                                                const float* __restrict__ kn) {
    extern __shared__ char dsm[];
    const __half* B;
    __half* C;
    const float* nw;
    float nsc;
    switch (blockIdx.z) {
        case 0: B = g_Wq16; C = g_q16; nw = qn; nsc = 0.125f; break;
        case 1: B = g_Wk16; C = g_k16; nw = kn; nsc = 1.0f; break;
        default: B = g_Wv16; C = g_v16; nw = nullptr; nsc = 1.0f; break;
    }
    dense_core(g_x16, B, nullptr, C, nullptr, nullptr, nw, nsc, Dd, Dd,
               blockIdx.x << 7, blockIdx.y << 7, dsm);
}

// ---------------- flash attention ----------------
__global__ void __launch_bounds__(256) fmha_k() {
    extern __shared__ __half sm[];
    const uint32_t sb = smem_u32(sm);
    const int z = blockIdx.y, b = z >> 4, h = z & 15;
    const int m0 = blockIdx.x << 7;
    const int tid = threadIdx.x, lane = tid & 31, wm = tid >> 5;
    const __half* Q = g_q16 + (size_t)b * Ss * Dd + h * HDd;
    const __half* Kp = g_k16 + (size_t)b * Ss * Dd + h * HDd;
    const __half* Vp = g_v16 + (size_t)b * Ss * Dd + h * HDd;

    {
#pragma unroll
        for (int i = 0; i < 4; i++) {
            int c = tid + (i << 8);
            int row = c >> 3, ch = (c & 7) << 3;
            CP16(sb + (uint32_t)(row * 72 + ch) * 2, Q + (size_t)(m0 + row) * Dd + ch);
        }
#pragma unroll
        for (int i = 0; i < 4; i++) {
            int c = tid + (i << 8);
            int row = c >> 3, ch = (c & 7) << 3;
            CP16(sb + (uint32_t)(FK0 + row * 72 + ch) * 2, Kp + (size_t)row * Dd + ch);
            CP16(sb + (uint32_t)(FV0 + row * 72 + ch) * 2, Vp + (size_t)row * Dd + ch);
        }
        CPCOMMIT();
    }
    uint32_t aq[4][4];
    float o_acc[8][4];
#pragma unroll
    for (int i = 0; i < 8; i++)
#pragma unroll
        for (int j = 0; j < 4; j++) o_acc[i][j] = 0.f;
    float m_prev0 = -1e30f, m_prev1 = -1e30f, l0 = 0.f, l1 = 0.f;

    for (int it = 0; it < 8; it++) {
        if (it < 7) {
            uint32_t kb = sb + (uint32_t)(FK0 + ((it + 1) & 1) * FKV) * 2;
            uint32_t vb = sb + (uint32_t)(FV0 + ((it + 1) & 1) * FKV) * 2;
            int s0 = (it + 1) << 7;
#pragma unroll
            for (int i = 0; i < 4; i++) {
                int c = tid + (i << 8);
                int row = c >> 3, ch = (c & 7) << 3;
                CP16(kb + (uint32_t)(row * 72 + ch) * 2, Kp + (size_t)(s0 + row) * Dd + ch);
                CP16(vb + (uint32_t)(row * 72 + ch) * 2, Vp + (size_t)(s0 + row) * Dd + ch);
            }
        }
        CPCOMMIT();
        CPWAIT1();
        __syncthreads();
        if (it == 0) {
#pragma unroll
            for (int kb = 0; kb < 4; kb++)
                ldm4(aq[kb], sb + (uint32_t)((wm * 16 + (lane & 15)) * 72 +
                                             kb * 16 + (lane >> 4) * 8) * 2);
        }
        const uint32_t kbase = sb + (uint32_t)(FK0 + (it & 1) * FKV) * 2;
        const uint32_t vbase = sb + (uint32_t)(FV0 + (it & 1) * FKV) * 2;
        float s_acc[16][4];
#pragma unroll
        for (int i = 0; i < 16; i++)
#pragma unroll
            for (int j = 0; j < 4; j++) s_acc[i][j] = 0.f;
#pragma unroll
        for (int kb = 0; kb < 4; kb++)
#pragma unroll
            for (int nb2 = 0; nb2 < 8; nb2++) {
                uint32_t bk[4];
                ldm4(bk, kbase + (uint32_t)((nb2 * 16 + ((lane >> 4) & 1) * 8 + (lane & 7)) * 72 +
                                            kb * 16 + ((lane >> 3) & 1) * 8) * 2);
                mma_f16(s_acc[nb2 * 2], aq[kb], bk);
                mma_f16(s_acc[nb2 * 2 + 1], aq[kb], bk + 2);
            }
        float mx0 = -1e30f, mx1 = -1e30f;
#pragma unroll
        for (int t = 0; t < 16; t++) {
            mx0 = fmaxf(mx0, fmaxf(s_acc[t][0], s_acc[t][1]));
            mx1 = fmaxf(mx1, fmaxf(s_acc[t][2], s_acc[t][3]));
        }
        mx0 = fmaxf(mx0, __shfl_xor_sync(0xffffffffu, mx0, 1));
        mx0 = fmaxf(mx0, __shfl_xor_sync(0xffffffffu, mx0, 2));
        mx1 = fmaxf(mx1, __shfl_xor_sync(0xffffffffu, mx1, 1));
        mx1 = fmaxf(mx1, __shfl_xor_sync(0xffffffffu, mx1, 2));
        float mn0 = fmaxf(m_prev0, mx0), mn1 = fmaxf(m_prev1, mx1);
        float sc0 = fexp(m_prev0 - mn0), sc1 = fexp(m_prev1 - mn1);
        m_prev0 = mn0; m_prev1 = mn1;
        float rs0 = 0.f, rs1 = 0.f;
#pragma unroll
        for (int t = 0; t < 16; t++) {
            s_acc[t][0] = fexp(s_acc[t][0] - mn0);
            s_acc[t][1] = fexp(s_acc[t][1] - mn0);
            s_acc[t][2] = fexp(s_acc[t][2] - mn1);
            s_acc[t][3] = fexp(s_acc[t][3] - mn1);
            rs0 += s_acc[t][0] + s_acc[t][1];
            rs1 += s_acc[t][2] + s_acc[t][3];
        }
        rs0 += __shfl_xor_sync(0xffffffffu, rs0, 1);
        rs0 += __shfl_xor_sync(0xffffffffu, rs0, 2);
        rs1 += __shfl_xor_sync(0xffffffffu, rs1, 1);
        rs1 += __shfl_xor_sync(0xffffffffu, rs1, 2);
        l0 = l0 * sc0 + rs0;
        l1 = l1 * sc1 + rs1;
#pragma unroll
        for (int ot = 0; ot < 8; ot++) {
            o_acc[ot][0] *= sc0; o_acc[ot][1] *= sc0;
            o_acc[ot][2] *= sc1; o_acc[ot][3] *= sc1;
        }
#pragma unroll
        for (int pb = 0; pb < 8; pb++) {
            uint32_t ap[4];
            ap[0] = pack_h2(s_acc[2 * pb][0], s_acc[2 * pb][1]);
            ap[1] = pack_h2(s_acc[2 * pb][2], s_acc[2 * pb][3]);
            ap[2] = pack_h2(s_acc[2 * pb + 1][0], s_acc[2 * pb + 1][1]);
            ap[3] = pack_h2(s_acc[2 * pb + 1][2], s_acc[2 * pb + 1][3]);
#pragma unroll
            for (int nb2 = 0; nb2 < 4; nb2++) {
                uint32_t bv[4];
                ldm4t(bv, vbase + (uint32_t)((pb * 16 + (lane & 7) + ((lane >> 3) & 1) * 8) * 72 +
                                             nb2 * 16 + (lane >> 4) * 8) * 2);
                mma_f16(o_acc[nb2 * 2], ap, bv);
                mma_f16(o_acc[nb2 * 2 + 1], ap, bv + 2);
            }
        }
        __syncthreads();
    }
    const float inv0 = 1.f / l0, inv1 = 1.f / l1;
    __half* O = g_o16 + (size_t)b * Ss * Dd + h * HDd;
    const int r = m0 + wm * 16 + (lane >> 2), c2 = (lane & 3) * 2;
#pragma unroll
    for (int ot = 0; ot < 8; ot++) {
        int col = ot * 8 + c2;
        *(uint32_t*)(O + (size_t)r * Dd + col) =
            pack_h2(o_acc[ot][0] * inv0, o_acc[ot][1] * inv0);
        *(uint32_t*)(O + (size_t)(r + 8) * Dd + col) =
            pack_h2(o_acc[ot][2] * inv1, o_acc[ot][3] * inv1);
    }
}

// ---------------- MoE gate/up k64, 3-stage + SiLU -> fp16 h ----------------
__global__ void __launch_bounds__(256) moe_gu16() {
    extern __shared__ __half sm[];
    __shared__ int toks[128];
    const int e = blockIdx.z;
    const int cnt = g_cnt[e];
    const int m0 = blockIdx.x << 7;
    if (m0 >= cnt) return;
    const int n0 = blockIdx.y << 7;
    const uint32_t sb = smem_u32(sm);
    const int tid = threadIdx.x, lane = tid & 31, wid = tid >> 5;
    const int wm = wid & 3, wn = wid >> 2;
    if (tid < 128) toks[tid] = g_assign[e * CAP + min(m0 + tid, cnt - 1)];
    __syncthreads();

    const size_t eo = (size_t)e * Dd * Ff;
    const __half* G = g_Wg16 + eo;
    const __half* U = g_Wu16 + eo;

    float ag[2][8][4], au[2][8][4];
#pragma unroll
    for (int a = 0; a < 2; a++)
#pragma unroll
        for (int c = 0; c < 8; c++)
#pragma unroll
            for (int d = 0; d < 4; d++) { ag[a][c][d] = 0.f; au[a][c][d] = 0.f; }

    const int ra = tid >> 3, ca = (tid & 7) << 3;
    const int rb = tid >> 4, cb = (tid & 15) << 3;

    auto issue = [&](int stg) {
        uint32_t base = sb + (uint32_t)(stg % 3) * STEg * 2;
        int k0 = stg << 6;
#pragma unroll
        for (int i = 0; i < 4; i++)
            CP16(base + (uint32_t)((ra + i * 32) * RS + ca) * 2,
                 g_xt16 + (size_t)toks[ra + i * 32] * Dd + k0 + ca);
#pragma unroll
        for (int i = 0; i < 4; i++) {
            CP16(base + (uint32_t)(OFG + (rb + i * 16) * RSB + cb) * 2,
                 G + (size_t)(k0 + rb + i * 16) * Ff + n0 + cb);
            CP16(base + (uint32_t)(OFU + (rb + i * 16) * RSB + cb) * 2,
                 U + (size_t)(k0 + rb + i * 16) * Ff + n0 + cb);
        }
    };
    issue(0); CPCOMMIT();
    issue(1); CPCOMMIT();

    const int nb = Dd >> 6;  // 16
    for (int it = 0; it < nb; it++) {
        if (it + 2 < nb) issue(it + 2);
        CPCOMMIT();
        CPWAIT2();
        __syncthreads();
        uint32_t base = sb + (uint32_t)(it % 3) * STEg * 2;
#pragma unroll
        for (int ks = 0; ks < 4; ks++) {
            uint32_t a[2][4];
#pragma unroll
            for (int mt = 0; mt < 2; mt++)
                ldm4(a[mt], base + (uint32_t)((wm * 32 + mt * 16 + (lane & 15)) * RS +
                                              ks * 16 + (lane >> 4) * 8) * 2);
            uint32_t roff = (uint32_t)((ks * 16 + (lane & 7) + ((lane >> 3) & 1) * 8) * RSB) * 2;
            uint32_t coff[4];
#pragma unroll
            for (int bt = 0; bt < 4; bt++)
                coff[bt] = (uint32_t)(wn * 64 + bt * 16 + (lane >> 4) * 8) * 2;
            {
                uint32_t bg[4][4];
#pragma unroll
                for (int bt = 0; bt < 4; bt++)
                    ldm4t(bg[bt], base + OFG * 2 + roff + coff[bt]);
#pragma unroll
                for (int mt = 0; mt < 2; mt++)
#pragma unroll
                    for (int nt = 0; nt < 8; nt++)
                        mma_f16(ag[mt][nt], a[mt], &bg[nt >> 1][(nt & 1) * 2]);
            }
            {
                uint32_t bu[4][4];
#pragma unroll
                for (int bt = 0; bt < 4; bt++)
                    ldm4t(bu[bt], base + OFU * 2 + roff + coff[bt]);
#pragma unroll
                for (int mt = 0; mt < 2; mt++)
#pragma unroll
                    for (int nt = 0; nt < 8; nt++)
                        mma_f16(au[mt][nt], a[mt], &bu[nt >> 1][(nt & 1) * 2]);
            }
        }
        __syncthreads();
    }
    const int lr = lane >> 2, lc2 = (lane & 3) * 2;
#pragma unroll
    for (int mt = 0; mt < 2; mt++)
#pragma unroll
        for (int nt = 0; nt < 8; nt++) {
            int r = m0 + wm * 32 + mt * 16 + lr;
            int col = n0 + wn * 64 + nt * 8 + lc2;
#pragma unroll
            for (int half = 0; half < 2; half++) {
                int rr = r + half * 8;
                if (rr < cnt) {
                    float gv0 = ag[mt][nt][half * 2], gv1 = ag[mt][nt][half * 2 + 1];
                    float uv0 = au[mt][nt][half * 2], uv1 = au[mt][nt][half * 2 + 1];
                    float v0 = gv0 * frcp(1.f + fexp(-gv0)) * uv0;
                    float v1 = gv1 * frcp(1.f + fexp(-gv1)) * uv1;
                    *(uint32_t*)(g_h16 + ((size_t)e * CAP + rr) * Ff + col) = pack_h2(v0, v1);
                }
            }
        }
}

// ---------------- MoE down k64 -> fp16 moeout (slot rows) ----------------
__global__ void __launch_bounds__(256, 2) moe_down16() {
    extern __shared__ __half sm[];
    const int e = blockIdx.z;
    const int cnt = g_cnt[e];
    const int m0 = blockIdx.x << 7;
    if (m0 >= cnt) return;
    const int n0 = blockIdx.y << 7;
    const uint32_t sb = smem_u32(sm);
    const int tid = threadIdx.x, lane = tid & 31, wid = tid >> 5;
    const int wm = wid & 3, wn = wid >> 2;
    const int cm1 = cnt - 1;

    const __half* A = g_h16 + (size_t)e * CAP * Ff;
    const __half* B = g_Wd16 + (size_t)e * Ff * Dd;

    float acc[2][8][4];
#pragma unroll
    for (int a = 0; a < 2; a++)
#pragma unroll
        for (int c = 0; c < 8; c++)
#pragma unroll
            for (int d = 0; d < 4; d++) acc[a][c][d] = 0.f;

    const int ra = tid >> 3, ca = (tid & 7) << 3;
    const int rb = tid >> 4, cb = (tid & 15) << 3;
    {
        uint32_t base = sb;
#pragma unroll
        for (int i = 0; i < 4; i++)
            CP16(base + (uint32_t)((ra + i * 32) * RS + ca) * 2,
                 A + (size_t)min(m0 + ra + i * 32, cm1) * Ff + ca);
#pragma unroll
        for (int i = 0; i < 4; i++)
            CP16(base + (uint32_t)(OFB + (rb + i * 16) * RSB + cb) * 2,
                 B + (size_t)(rb + i * 16) * Dd + n0 + cb);
        CPCOMMIT();
    }
    const int nb = Ff >> 6;
    for (int it = 0; it < nb; it++) {
        if (it + 1 < nb) {
            uint32_t base = sb + (uint32_t)((it + 1) & 1) * STEd * 2;
            int k0 = (it + 1) << 6;
#pragma unroll
            for (int i = 0; i < 4; i++)
                CP16(base + (uint32_t)((ra + i * 32) * RS + ca) * 2,
                     A + (size_t)min(m0 + ra + i * 32, cm1) * Ff + k0 + ca);
#pragma unroll
            for (int i = 0; i < 4; i++)
                CP16(base + (uint32_t)(OFB + (rb + i * 16) * RSB + cb) * 2,
                     B + (size_t)(k0 + rb + i * 16) * Dd + n0 + cb);
        }
        CPCOMMIT();
        CPWAIT1();
        __syncthreads();
        uint32_t base = sb + (uint32_t)(it & 1) * STEd * 2;
#pragma unroll
        for (int ks = 0; ks < 4; ks++) {
            uint32_t a[2][4];
#pragma unroll
            for (int mt = 0; mt < 2; mt++)
                ldm4(a[mt], base + (uint32_t)((wm * 32 + mt * 16 + (lane & 15)) * RS +
                                              ks * 16 + (lane >> 4) * 8) * 2);
            uint32_t bq[4][4];
#pragma unroll
            for (int bt = 0; bt < 4; bt++)
                ldm4t(bq[bt], base + (uint32_t)(OFB +
                                                (ks * 16 + (lane & 7) + ((lane >> 3) & 1) * 8) * RSB +
                                                wn * 64 + bt * 16 + (lane >> 4) * 8) * 2);
#pragma unroll
            for (int mt = 0; mt < 2; mt++)
#pragma unroll
                for (int nt = 0; nt < 8; nt++)
                    mma_f16(acc[mt][nt], a[mt], &bq[nt >> 1][(nt & 1) * 2]);
        }
        __syncthreads();
    }
    const int lr = lane >> 2, lc2 = (lane & 3) * 2;
#pragma unroll
    for (int mt = 0; mt < 2; mt++)
#pragma unroll
        for (int half = 0; half < 2; half++) {
            int r = m0 + wm * 32 + mt * 16 + lr + half * 8;
            if (r < cnt) {
                __half* op = g_moeout16 + ((size_t)e * CAP + r) * Dd;
#pragma unroll
                for (int nt = 0; nt < 8; nt++) {
                    int col = n0 + wn * 64 + nt * 8 + lc2;
                    *(uint32_t*)(op + col) = pack_h2(acc[mt][nt][half * 2],
                                                     acc[mt][nt][half * 2 + 1]);
                }
            }
        }
}

// ---------------- final gather (fp16 moeout) + counter reset for next replay ----------------
__global__ void final_k(float* __restrict__ out) {
    const size_t i4 = ((size_t)blockIdx.x * 256 + threadIdx.x) * 4;
    const int t = (int)(i4 >> 10);
    const int c = (int)(i4 & 1023);
    const int s0 = g_slotid[t * 2 + 0], s1 = g_slotid[t * 2 + 1];
    const float w0 = g_topw[t * 2 + 0], w1 = g_topw[t * 2 + 1];
    float4 hv = *(const float4*)(g_hidden + i4);
    uint2 m0p = *(const uint2*)(g_moeout16 + (size_t)s0 * Dd + c);
    uint2 m1p = *(const uint2*)(g_moeout16 + (size_t)s1 * Dd + c);
    __half2 m0a = *(__half2*)&m0p.x, m0b = *(__half2*)&m0p.y;
    __half2 m1a = *(__half2*)&m1p.x, m1b = *(__half2*)&m1p.y;
    hv.x += w0 * __half2float(m0a.x) + w1 * __half2float(m1a.x);
    hv.y += w0 * __half2float(m0a.y) + w1 * __half2float(m1a.y);
    hv.z += w0 * __half2float(m0b.x) + w1 * __half2float(m1b.x);
    hv.w += w0 * __half2float(m0b.y) + w1 * __half2float(m1b.y);
    *(float4*)(out + i4) = hv;
    // reset expert counters for the next graph replay (globals start zeroed at load)
    if (blockIdx.x == 0 && threadIdx.x < Ee) g_cnt[threadIdx.x] = 0;
}

// ---------------- launch ----------------
extern "C" void kernel_launch(void* const* d_in, const int* in_sizes, int n_in,
                              void* d_out, int out_size) {
    (void)in_sizes; (void)n_in;
    const float* hs    = (const float*)d_in[0];
    const float* ln1   = (const float*)d_in[1];
    const float* ln2   = (const float*)d_in[2];
    const float* Wq    = (const float*)d_in[3];
    const float* Wk    = (const float*)d_in[4];
    const float* Wv    = (const float*)d_in[5];
    const float* Wo    = (const float*)d_in[6];
    const float* qn    = (const float*)d_in[7];
    const float* kn    = (const float*)d_in[8];
    const float* gamma = (const float*)d_in[9];
    const float* gw    = (const float*)d_in[10];
    const float* Wg    = (const float*)d_in[11];
    const float* Wu    = (const float*)d_in[12];
    const float* Wd    = (const float*)d_in[13];
    float* out = (float*)d_out;

    float* p_hidden;
    cudaGetSymbolAddress((void**)&p_hidden, g_hidden);

    __half *wg16, *wu16, *wd16, *wo16, *x16, *o16, *xt16;
    cudaGetSymbolAddress((void**)&wg16, g_Wg16);
    cudaGetSymbolAddress((void**)&wu16, g_Wu16);
    cudaGetSymbolAddress((void**)&wd16, g_Wd16);
    cudaGetSymbolAddress((void**)&wo16, g_Wo16);
    cudaGetSymbolAddress((void**)&x16, g_x16);
    cudaGetSymbolAddress((void**)&o16, g_o16);
    cudaGetSymbolAddress((void**)&xt16, g_xt16);

    cudaFuncSetAttribute(hgemm16, cudaFuncAttributeMaxDynamicSharedMemorySize, SMEMd);
    cudaFuncSetAttribute(qkv_k, cudaFuncAttributeMaxDynamicSharedMemorySize, SMEMd);
    cudaFuncSetAttribute(moe_down16, cudaFuncAttributeMaxDynamicSharedMemorySize, SMEMd);
    cudaFuncSetAttribute(moe_gu16, cudaFuncAttributeMaxDynamicSharedMemorySize, SMEMg3);
    cudaFuncSetAttribute(fmha_k, cudaFuncAttributeMaxDynamicSharedMemorySize, SMEMf);

    // side streams + events (created once; reused across captures)
    static cudaStream_t s2 = 0, s3 = 0;
    static cudaEvent_t evF = 0, evJ = 0, evJ3 = 0;
    static int sinit = 0;
    if (!sinit) {
        if (cudaStreamCreateWithFlags(&s2, cudaStreamNonBlocking) != cudaSuccess) s2 = 0;
        if (cudaStreamCreateWithFlags(&s3, cudaStreamNonBlocking) != cudaSuccess) s3 = 0;
        cudaEventCreateWithFlags(&evF, cudaEventDisableTiming);
        cudaEventCreateWithFlags(&evJ, cudaEventDisableTiming);
        cudaEventCreateWithFlags(&evJ3, cudaEventDisableTiming);
        sinit = 1;
    }

    // fork FIRST: big MoE weight converts on s2; small converts on s3
    cudaEventRecord(evF, 0);
    cudaStreamWaitEvent(s2, evF, 0);
    cudaStreamWaitEvent(s3, evF, 0);
    wconv_k<<<(int)((size_t)Ee * Dd * Ff / 2048), 256, 0, s2>>>(Wg, wg16);
    wconv_k<<<(int)((size_t)Ee * Dd * Ff / 2048), 256, 0, s2>>>(Wu, wu16);
    wconv_k<<<(int)((size_t)Ee * Ff * Dd / 2048), 256, 0, s2>>>(Wd, wd16);
    cudaEventRecord(evJ, s2);
    wconv4_k<<<dim3(Dd * Dd / 2048, 1, 4), 256, 0, s3>>>(Wq, Wk, Wv, Wo);
    cudaEventRecord(evJ3, s3);

    // --- attention branch ---
    rmsnorm_h<<<Tt, 256>>>(hs, ln1, x16);
    cudaStreamWaitEvent(0, evJ3, 0);   // QKV/Wo fp16 weights ready
    qkv_k<<<dim3(32, 8, 3), 256, SMEMd>>>(qn, kn);
    fmha_k<<<dim3(8, 64), 256, SMEMf>>>();
    hgemm16<<<dim3(32, 8), 256, SMEMd>>>(o16, wo16, p_hidden, nullptr, hs, gamma, nullptr, 1.f, Dd, Dd);

    // --- MoE branch (serial, full-z launches: best measured packing) ---
    int write_logits = (out_size >= Tt * Dd + Tt * Ee) ? 1 : 0;
    rmsnorm_router_k<<<Tt, 256>>>(p_hidden, ln2, gw, xt16, out + (size_t)Tt * Dd, write_logits);
    cudaStreamWaitEvent(0, evJ, 0);   // MoE weights ready
    moe_gu16<<<dim3(CAP / 128, Ff / 128, Ee), 256, SMEMg3>>>();
    moe_down16<<<dim3(CAP / 128, Dd / 128, Ee), 256, SMEMd>>>();
    final_k<<<Tt * Dd / 1024, 256>>>(out);
}